// round 6
// baseline (speedup 1.0000x reference)
#include <cuda_runtime.h>

#define BB 4
#define CC 64
#define NN 8192
#define OO 128
#define KK 20

typedef unsigned long long u64;

// Scratch (static device allocations — no cudaMalloc anywhere)
__device__ __align__(16) float g_xt[(size_t)BB * NN * CC];  // x^T: [b][n][c]
__device__ float g_xx[BB * NN];                 // 0.5 * squared norms
__device__ int   g_knn[(size_t)BB * NN * KK];   // top-K indices
__device__ float g_W1at[CC * CC];               // [j][c] = W1[c][j],    c<64
__device__ float g_W1bt[CC * CC];               // [j][c] = W1[c][64+j], c<64
__device__ float g_W2t[2 * CC * OO];            // [c][o] = W2[o][c]

// ---- packed fp32x2 helpers (bit-exact fp32, 2 MACs/issue) -----------------
__device__ __forceinline__ u64 fma2(u64 a, u64 b, u64 c) {
    u64 d; asm("fma.rn.f32x2 %0, %1, %2, %3;" : "=l"(d) : "l"(a), "l"(b), "l"(c));
    return d;
}
__device__ __forceinline__ u64 add2(u64 a, u64 b) {
    u64 d; asm("add.rn.f32x2 %0, %1, %2;" : "=l"(d) : "l"(a), "l"(b));
    return d;
}
__device__ __forceinline__ u64 pack2(float lo, float hi) {
    u64 d; asm("mov.b64 %0, {%1, %2};" : "=l"(d) : "f"(lo), "f"(hi));
    return d;
}
__device__ __forceinline__ void unpack2(float& lo, float& hi, u64 v) {
    asm("mov.b64 {%0, %1}, %2;" : "=f"(lo), "=f"(hi) : "l"(v));
}

// ---------------------------------------------------------------------------
// Prep: tiled transpose x -> xt[b][n][c] (coalesced both sides) + 0.5*norms
// ---------------------------------------------------------------------------
__global__ __launch_bounds__(256) void prep_x_kernel(const float* __restrict__ x) {
    int b = blockIdx.y;
    int n0 = blockIdx.x * 32;
    __shared__ float sh[CC][33];
    const float* xb = x + (size_t)b * CC * NN;
    int tid = threadIdx.x;
#pragma unroll
    for (int it = 0; it < 8; it++) {
        int e = it * 256 + tid;
        int c = e >> 5, nl = e & 31;
        sh[c][nl] = __ldg(&xb[(size_t)c * NN + n0 + nl]);  // coalesced
    }
    __syncthreads();
#pragma unroll
    for (int it = 0; it < 8; it++) {
        int e = it * 256 + tid;
        int nl = e >> 6, c = e & 63;
        g_xt[((size_t)b * NN + n0 + nl) * CC + c] = sh[c][nl];  // coalesced
    }
    if (tid < 32) {
        float s = 0.f;
#pragma unroll
        for (int c = 0; c < CC; c++) { float v = sh[c][tid]; s += v * v; }
        g_xx[b * NN + n0 + tid] = 0.5f * s;
    }
}

// ---------------------------------------------------------------------------
// Prep weights. Only W1 rows c<64 needed (softmax over k sums to 1, so gate
// columns c>=64 contribute exactly center).
// ---------------------------------------------------------------------------
__global__ void prep_w_kernel(const float* __restrict__ W1,
                              const float* __restrict__ W2) {
    int t = blockIdx.x * 256 + threadIdx.x;  // 0..32767
    if (t < 128 * 128) {
        int c = t >> 7, j = t & 127;
        float v = W1[t];
        if (c < CC) {
            if (j < CC) g_W1at[j * CC + c] = v;
            else        g_W1bt[(j - CC) * CC + c] = v;
        }
    } else {
        int t2 = t - 128 * 128;
        int o = t2 >> 7, c2 = t2 & 127;
        g_W2t[c2 * OO + o] = W2[t2];
    }
}

// ---------------------------------------------------------------------------
// Top-K insertion (sorted desc, static indices). Strict '>' keeps earliest
// index on ties, matching jax.lax.top_k.
// ---------------------------------------------------------------------------
__device__ __forceinline__ void topk_insert(float (&vals)[KK], int (&idxs)[KK],
                                            float v, int j) {
    vals[KK - 1] = v;
    idxs[KK - 1] = j;
#pragma unroll
    for (int p = KK - 1; p > 0; --p) {
        if (vals[p] > vals[p - 1]) {
            float tv = vals[p]; vals[p] = vals[p - 1]; vals[p - 1] = tv;
            int   ti = idxs[p]; idxs[p] = idxs[p - 1]; idxs[p - 1] = ti;
        }
    }
}

// ---------------------------------------------------------------------------
// KNN: 2 lanes per query (lane pair splits the 64 dims), 64 queries/block,
// 512 blocks total -> 3-4 resident blocks/SM (regs ~95, 5/SM capacity),
// 12-16 warps/SM so the FFMA2 pipe can saturate.
// Per candidate per lane: 8 LDS.128 + 16 FFMA2 + shfl-combine + guard.
// Lane pairs compute identical rank -> insert path stays pair-convergent.
// rank = dot - 0.5*||xj||^2  (monotone in pd; xxi constant per query).
// ---------------------------------------------------------------------------
__global__ __launch_bounds__(128) void knn_kernel() {
    int b = blockIdx.y;
    int tid = threadIdx.x;
    int half = tid & 1;        // which 32-dim half this lane owns
    int i = blockIdx.x * 64 + (tid >> 1);
    __shared__ __align__(16) float shx[128][CC];
    __shared__ float shxx[128];
    const float* xtb = g_xt + (size_t)b * NN * CC;

    // load this lane's half of the query row: 8 x float4 = 16 f32x2
    u64 xi2[16];
    const float4* xir = (const float4*)(xtb + (size_t)i * CC + half * 32);
#pragma unroll
    for (int q = 0; q < 8; q++) {
        float4 t = __ldg(&xir[q]);
        xi2[2 * q + 0] = pack2(t.x, t.y);
        xi2[2 * q + 1] = pack2(t.z, t.w);
    }

    float vals[KK]; int idxs[KK];
#pragma unroll
    for (int k = 0; k < KK; k++) { vals[k] = -3.0e38f; idxs[k] = 0; }

    for (int j0 = 0; j0 < NN; j0 += 128) {
        __syncthreads();
        const float4* src = (const float4*)(xtb + (size_t)j0 * CC);
        float4* dst = (float4*)shx;
#pragma unroll
        for (int r = 0; r < 16; r++) {
            int lin = r * 128 + tid;
            dst[lin] = __ldg(&src[lin]);
        }
        shxx[tid] = g_xx[b * NN + j0 + tid];
        __syncthreads();

        for (int jl = 0; jl < 128; jl++) {
            const ulonglong2* row = (const ulonglong2*)(shx[jl] + half * 32);
            u64 a0 = 0ull, a1 = 0ull, a2 = 0ull, a3 = 0ull;
#pragma unroll
            for (int q = 0; q < 4; q++) {
                ulonglong2 v0 = row[2 * q];
                ulonglong2 v1 = row[2 * q + 1];
                a0 = fma2(xi2[4 * q + 0], v0.x, a0);
                a1 = fma2(xi2[4 * q + 1], v0.y, a1);
                a2 = fma2(xi2[4 * q + 2], v1.x, a2);
                a3 = fma2(xi2[4 * q + 3], v1.y, a3);
            }
            a0 = add2(a0, a1);
            a2 = add2(a2, a3);
            a0 = add2(a0, a2);
            float lo, hi; unpack2(lo, hi, a0);
            float d = lo + hi;                               // my half-dot
            float dot = d + __shfl_xor_sync(0xffffffffu, d, 1);  // pair combine
            float rank = dot - shxx[jl];
            if (rank > vals[KK - 1]) topk_insert(vals, idxs, rank, j0 + jl);
        }
    }
    if (!half) {
        int* op = g_knn + ((size_t)b * NN + i) * KK;
#pragma unroll
        for (int k = 0; k < KK; k++) op[k] = idxs[k];
    }
}

// ---------------------------------------------------------------------------
// Fused MLP (exact round-2 code, known 358us): 4 points/block; thread
// (p = tid>>6, c = tid&63) owns column c (<64) of point p.
// ---------------------------------------------------------------------------
__global__ __launch_bounds__(256) void mlp_kernel(float* __restrict__ out) {
    int b = blockIdx.y;
    int n0 = blockIdx.x * 4;
    int tid = threadIdx.x;
    int p = tid >> 6, c = tid & 63;

    __shared__ __align__(16) float nbrT[4][CC][24];  // diff[j][k], pitch 24
    __shared__ float xi_sh[4][CC];
    __shared__ int   idx_sh[4][KK];
    __shared__ float g_sh[4][2 * CC];

    const float* xtb = g_xt + (size_t)b * NN * CC;

    if (tid < 4 * KK) {
        int pp = tid / KK, k = tid % KK;
        idx_sh[pp][k] = g_knn[((size_t)b * NN + n0 + pp) * KK + k];
    }
    xi_sh[p][c] = __ldg(&xtb[(size_t)(n0 + p) * CC + c]);
    __syncthreads();

    // gather neighbors and form diff = xj - xi, stored transposed [c][k]
    for (int pp = 0; pp < 4; pp++) {
        for (int e = tid; e < KK * CC; e += 256) {
            int k = e >> 6, cc = e & 63;
            nbrT[pp][cc][k] =
                __ldg(&xtb[(size_t)idx_sh[pp][k] * CC + cc]) - xi_sh[pp][cc];
        }
    }
    __syncthreads();

    // h[k] for this thread's column c (<64) of point p
    float h[KK];
#pragma unroll
    for (int k = 0; k < KK; k++) h[k] = 0.f;
    float base = 0.f;
#pragma unroll 8
    for (int j = 0; j < CC; j++) {
        float w  = __ldg(&g_W1at[j * CC + c]);          // coalesced, L1-hot
        base    += __ldg(&g_W1bt[j * CC + c]) * xi_sh[p][j];
        const float4* f4 = (const float4*)nbrT[p][j];   // broadcast
#pragma unroll
        for (int q = 0; q < 5; q++) {
            float4 f = f4[q];
            h[4 * q + 0] += f.x * w;
            h[4 * q + 1] += f.y * w;
            h[4 * q + 2] += f.z * w;
            h[4 * q + 3] += f.w * w;
        }
    }

    // softmax over k, then g
    float m = -3.0e38f;
#pragma unroll
    for (int k = 0; k < KK; k++) { h[k] += base; m = fmaxf(m, h[k]); }
    float s = 0.f;
#pragma unroll
    for (int k = 0; k < KK; k++) { h[k] = __expf(h[k] - m); s += h[k]; }
    float inv = 1.f / s;
    float gdiff = 0.f;
#pragma unroll
    for (int k = 0; k < KK; k++) gdiff += nbrT[p][c][k] * h[k];
    g_sh[p][c]      = gdiff * inv;
    g_sh[p][CC + c] = xi_sh[p][c];  // softmax sums to 1 -> center passthrough
    __syncthreads();

    // out[o] = sum_c W2[o][c] * g[c]
    int o = tid & 127;
    int pb = (tid >> 7) * 2;
    for (int r = 0; r < 2; r++) {
        int pp = pb + r;
        float acc = 0.f;
#pragma unroll 16
        for (int cc = 0; cc < 2 * CC; cc++)
            acc += __ldg(&g_W2t[cc * OO + o]) * g_sh[pp][cc];
        out[(size_t)b * OO * NN + (size_t)o * NN + (n0 + pp)] = acc;
    }
}

// ---------------------------------------------------------------------------
extern "C" void kernel_launch(void* const* d_in, const int* in_sizes, int n_in,
                              void* d_out, int out_size) {
    const float* x  = (const float*)d_in[0];
    const float* W1 = (const float*)d_in[1];
    const float* W2 = (const float*)d_in[2];
    float* out = (float*)d_out;

    prep_x_kernel<<<dim3(NN / 32, BB), 256>>>(x);
    prep_w_kernel<<<128, 256>>>(W1, W2);
    knn_kernel<<<dim3(NN / 64, BB), 128>>>();
    mlp_kernel<<<dim3(NN / 4, BB), 256>>>(out);
}